// round 2
// baseline (speedup 1.0000x reference)
#include <cuda_runtime.h>

#define NBLOCKS  1024
#define NTHREADS 256

// Per-block partial sums. Fully overwritten on every call -> no zeroing needed.
__device__ float        g_pts[NBLOCKS];
__device__ float        g_prs[NBLOCKS];
__device__ unsigned int g_ctr = 0;   // reset by the last block each call

__device__ __forceinline__ float wrap_angle(float a) {
    const float PI  = 3.14159265358979323846f;
    const float TPI = 6.28318530717958647692f;
    a = (a >  PI) ? a - TPI : a;
    a = (a < -PI) ? a + TPI : a;
    return a;
}

__device__ __forceinline__ void accum(float4 p, float4 t, unsigned v,
                                      float& ts, float& rs) {
    // First channel of float4 #v is (4v) % 6; rotation-lane mask per v%3:
    //   m=0 -> channels 0,1,2,3 -> rot mask 0b1000
    //   m=1 -> channels 4,5,0,1 -> rot mask 0b0011
    //   m=2 -> channels 2,3,4,5 -> rot mask 0b1110
    unsigned m     = v % 3u;
    unsigned rmask = (m == 0u) ? 0x8u : ((m == 1u) ? 0x3u : 0xEu);

    float pe[4] = {p.x, p.y, p.z, p.w};
    float te[4] = {t.x, t.y, t.z, t.w};

    #pragma unroll
    for (int j = 0; j < 4; j++) {
        bool  rot = (rmask >> j) & 1u;
        float d   = pe[j] - te[j];
        float dw  = wrap_angle(pe[j]) - wrap_angle(te[j]);
        float val = rot ? dw : d;
        float v2  = val * val;
        ts += rot ? 0.0f : v2;
        rs += rot ? v2   : 0.0f;
    }
}

__global__ void __launch_bounds__(NTHREADS)
wmse_kernel(const float4* __restrict__ p4, const float4* __restrict__ t4,
            unsigned n4, float* __restrict__ out) {
    const unsigned total = NBLOCKS * NTHREADS;
    unsigned tid = blockIdx.x * NTHREADS + threadIdx.x;

    float ts = 0.0f, rs = 0.0f;

    // Unrolled-by-4 grid-stride: issue 8 x 16B loads before any compute.
    unsigned v = tid;
    for (; v + 3u * total < n4; v += 4u * total) {
        float4 p0 = p4[v];
        float4 p1 = p4[v +      total];
        float4 p2 = p4[v + 2u * total];
        float4 p3 = p4[v + 3u * total];
        float4 t0 = t4[v];
        float4 t1 = t4[v +      total];
        float4 t2 = t4[v + 2u * total];
        float4 t3 = t4[v + 3u * total];
        accum(p0, t0, v,               ts, rs);
        accum(p1, t1, v +      total,  ts, rs);
        accum(p2, t2, v + 2u * total,  ts, rs);
        accum(p3, t3, v + 3u * total,  ts, rs);
    }
    for (; v < n4; v += total) {           // tail (empty for the bench shape)
        accum(p4[v], t4[v], v, ts, rs);
    }

    // Block reduction
    #pragma unroll
    for (int o = 16; o > 0; o >>= 1) {
        ts += __shfl_xor_sync(0xffffffffu, ts, o);
        rs += __shfl_xor_sync(0xffffffffu, rs, o);
    }
    __shared__ float sts[NTHREADS / 32];
    __shared__ float srs[NTHREADS / 32];
    int lane = threadIdx.x & 31;
    int warp = threadIdx.x >> 5;
    if (lane == 0) { sts[warp] = ts; srs[warp] = rs; }
    __syncthreads();

    __shared__ bool isLast;
    if (threadIdx.x == 0) {
        float bts = 0.0f, brs = 0.0f;
        #pragma unroll
        for (int w = 0; w < NTHREADS / 32; w++) { bts += sts[w]; brs += srs[w]; }
        g_pts[blockIdx.x] = bts;
        g_prs[blockIdx.x] = brs;
        __threadfence();
        unsigned prev = atomicAdd(&g_ctr, 1u);
        isLast = (prev == (unsigned)gridDim.x - 1u);
    }
    __syncthreads();

    // Last block: reduce the per-block partials and finalize.
    if (isLast) {
        __threadfence();
        float a = 0.0f, b = 0.0f;
        for (unsigned i = threadIdx.x; i < NBLOCKS; i += NTHREADS) {
            a += g_pts[i];
            b += g_prs[i];
        }
        #pragma unroll
        for (int o = 16; o > 0; o >>= 1) {
            a += __shfl_xor_sync(0xffffffffu, a, o);
            b += __shfl_xor_sync(0xffffffffu, b, o);
        }
        __syncthreads();                 // sts/srs reuse
        if (lane == 0) { sts[warp] = a; srs[warp] = b; }
        __syncthreads();
        if (threadIdx.x == 0) {
            float A = 0.0f, B = 0.0f;
            #pragma unroll
            for (int w = 0; w < NTHREADS / 32; w++) { A += sts[w]; B += srs[w]; }
            g_ctr = 0;                   // rearm for the next graph replay
            double cnt        = 2.0 * (double)n4;  // elements/2 = n4*4/2
            double trans_loss = (double)A / cnt;            // TRANS_WEIGHT=1
            double rot_loss   = ((double)B / cnt) * 100.0;  // ROT_WEIGHT=100
            out[0] = (float)(trans_loss + rot_loss);
            out[1] = (float)trans_loss;
            out[2] = (float)rot_loss;
        }
    }
}

extern "C" void kernel_launch(void* const* d_in, const int* in_sizes, int n_in,
                              void* d_out, int out_size) {
    const float4* pred4   = (const float4*)d_in[0];
    const float4* target4 = (const float4*)d_in[1];
    unsigned n4 = (unsigned)(in_sizes[0] / 4);

    wmse_kernel<<<NBLOCKS, NTHREADS>>>(pred4, target4, n4, (float*)d_out);
}